// round 3
// baseline (speedup 1.0000x reference)
#include <cuda_runtime.h>
#include <cuda_bf16.h>
#include <cstddef>

// ---------------------------------------------------------------------------
// DRNN: 2-layer SimpleRNN (tanh), B=512, T=512, D=64, H=100.
//   h1_t = tanh(x_t @ W1x + h1_{t-1} @ W1h + b1)
//   h2_t = tanh(h1_t @ W2x + h2_{t-1} @ W2h + b2)
//   out  = h2_T @ Wo + bo
// d_out layout: out[512] | h1_T[512*100] | h2_T[512*100]
//
//  1) precompute_xw: xw[t][b][u] = b1[u] + x_t@W1x (no time dep) -> scratch.
//  2) rnn_kernel: 128 blocks x 4 batch rows, 128 threads. Weights resident in
//     SMEM pre-paired over j ([j/2][u][2]) so the inner loop uses packed
//     fma.rn.f32x2 (FFMA2) — half the FMA issue slots of scalar. h state in
//     SMEM as [j/2][row][2] (double buffered -> 2 barriers/step); one
//     broadcast LDS.128 yields two rows' j-pairs as ready f32x2 operands.
// ---------------------------------------------------------------------------

#define T_STEPS 512
#define BATCH   512
#define IN_DIM  64
#define H       100
#define HP      128   // padded hidden (u dimension)
#define JP      (H/2) // 50 j-pairs

typedef unsigned long long u64t;

// scratch: [T][B][HP] floats = 134 MB
__device__ float g_xw[(size_t)T_STEPS * BATCH * HP];

__device__ __forceinline__ void ffma2(u64t& d, u64t a, u64t b) {
    // d.lo += a.lo*b.lo ; d.hi += a.hi*b.hi   (packed f32x2 FMA)
    asm("fma.rn.f32x2 %0, %1, %2, %0;" : "+l"(d) : "l"(a), "l"(b));
}
__device__ __forceinline__ u64t pack2(float lo, float hi) {
    u64t r;
    asm("mov.b64 %0, {%1, %2};" : "=l"(r) : "f"(lo), "f"(hi));
    return r;
}
__device__ __forceinline__ float sum2(u64t v) {
    float lo, hi;
    asm("mov.b64 {%0, %1}, %2;" : "=f"(lo), "=f"(hi) : "l"(v));
    return lo + hi;
}

// ---------------------------------------------------------------------------
// Kernel 1: precompute xw = b1 + x @ W1x   (grid: 512 t x 8 b-chunks of 64)
// ---------------------------------------------------------------------------
__global__ void __launch_bounds__(320) precompute_xw_kernel(
    const float* __restrict__ x,     // [B][T][D]
    const float* __restrict__ W1x,   // [D][H]
    const float* __restrict__ b1)    // [H]
{
    __shared__ __align__(16) float sW[IN_DIM * H];   // 6400
    __shared__ float sx[64 * IN_DIM];                // 4096
    __shared__ float sb1[H];

    const int t   = blockIdx.x;
    const int b0  = blockIdx.y * 64;
    const int tid = threadIdx.x;

    for (int i = tid; i < IN_DIM * H; i += 320) sW[i] = W1x[i];
    for (int i = tid; i < H; i += 320) sb1[i] = b1[i];
    for (int i = tid; i < 64 * IN_DIM; i += 320) {
        int bl = i >> 6, d = i & 63;
        sx[i] = x[(size_t)(b0 + bl) * (T_STEPS * IN_DIM) + (size_t)t * IN_DIM + d];
    }
    __syncthreads();

    // 1600 tasks = 64 rows * 25 u-groups (u = 4*ug), 5 per thread
    #pragma unroll
    for (int k = 0; k < 5; k++) {
        int task = tid + k * 320;
        int bl = task / 25;
        int ug = task % 25;
        int u  = ug * 4;
        float a0 = sb1[u], a1 = sb1[u + 1], a2 = sb1[u + 2], a3 = sb1[u + 3];
        #pragma unroll
        for (int d = 0; d < IN_DIM; d++) {
            float xv = sx[bl * IN_DIM + d];
            // d*100 + 4*ug : byte offset 400d + 16ug -> 16B aligned
            float4 w = *(const float4*)&sW[d * H + u];
            a0 += xv * w.x; a1 += xv * w.y; a2 += xv * w.z; a3 += xv * w.w;
        }
        size_t base = (size_t)t * (BATCH * HP) + (size_t)(b0 + bl) * HP + u;
        *(float4*)&g_xw[base] = make_float4(a0, a1, a2, a3);
    }
}

// ---------------------------------------------------------------------------
// Kernel 2: persistent recurrence. 128 blocks x 4 rows, 128 threads.
// Thread u computes hidden unit u for the block's 4 batch rows.
//
// SMEM float offsets:
//   weights (pair-major [jp][u][2], 50*128*2 = 12800 each):
//     sW1h @ 0, sW2x @ 12800, sW2h @ 25600
//   h state [2 bufs][jp][row][2] (stride 8 per jp, 400 per buf):
//     sh1 @ 38400 (800), sh2 @ 39200 (800)
//   sB2 @ 40000 (128), sWo @ 40128 (128)   -> total 40256 floats = 161024 B
// ---------------------------------------------------------------------------
#define SM_W1H 0
#define SM_W2X 12800
#define SM_W2H 25600
#define SM_H1  38400
#define SM_H2  39200
#define SM_B2  40000
#define SM_WO  40128
#define SM_FLOATS 40256
#define SMEM_BYTES (SM_FLOATS * 4)

__global__ void __launch_bounds__(128, 1) rnn_kernel(
    const float* __restrict__ W1h,  // [H][H]
    const float* __restrict__ W2x,  // [H][H]
    const float* __restrict__ W2h,  // [H][H]
    const float* __restrict__ b2,   // [H]
    const float* __restrict__ Wo,   // [H][1]
    const float* __restrict__ bo,   // [1]
    float* __restrict__ out)        // [512 + 51200 + 51200]
{
    extern __shared__ __align__(16) float sm[];
    float* sW1h = sm + SM_W1H;
    float* sW2x = sm + SM_W2X;
    float* sW2h = sm + SM_W2H;
    float* sh1  = sm + SM_H1;   // [2][400]
    float* sh2  = sm + SM_H2;   // [2][400]
    float* sB2  = sm + SM_B2;
    float* sWo  = sm + SM_WO;

    const int tid = threadIdx.x;          // 0..127 == u
    const int b0  = blockIdx.x * 4;       // 4 batch rows per block
    const int u   = tid;
    const bool active = (u < H);

    // Load weights in pair-major layout: s[jp*256 + u*2 + p] = W[(2jp+p)][u]
    for (int i = tid; i < JP * HP * 2; i += 128) {
        int jp = i >> 8;            // /256
        int rem = i & 255;
        int uu = rem >> 1;
        int p  = rem & 1;
        int j  = 2 * jp + p;
        bool v = (uu < H);
        sW1h[i] = v ? W1h[j * H + uu] : 0.0f;
        sW2x[i] = v ? W2x[j * H + uu] : 0.0f;
        sW2h[i] = v ? W2h[j * H + uu] : 0.0f;
    }
    sB2[tid] = (tid < H) ? b2[tid] : 0.0f;
    sWo[tid] = (tid < H) ? Wo[tid] : 0.0f;
    for (int i = tid; i < 800; i += 128) { sh1[i] = 0.0f; sh2[i] = 0.0f; }
    __syncthreads();

    const int jpH = (u >> 1) * 8 + (u & 1);  // this thread's h write base (+2r)

    // Prefetch xw for t=0 (4 rows)
    float xw0 = 0.f, xw1 = 0.f, xw2 = 0.f, xw3 = 0.f;
    if (active) {
        size_t base = (size_t)b0 * HP + u;
        xw0 = g_xw[base];
        xw1 = g_xw[base + HP];
        xw2 = g_xw[base + 2 * HP];
        xw3 = g_xw[base + 3 * HP];
    }

    for (int t = 0; t < T_STEPS; t++) {
        const int rb = (t & 1) * 400;        // read buffer
        const int wb = 400 - rb;             // write buffer
        const float* h1r = sh1 + rb;
        float*       h1w = sh1 + wb;
        const float* h2r = sh2 + rb;
        float*       h2w = sh2 + wb;

        // software-pipelined prefetch of next timestep's xw
        float nx0 = 0.f, nx1 = 0.f, nx2 = 0.f, nx3 = 0.f;
        if (active && (t + 1 < T_STEPS)) {
            size_t base = (size_t)(t + 1) * (BATCH * HP) + (size_t)b0 * HP + u;
            nx0 = g_xw[base];
            nx1 = g_xw[base + HP];
            nx2 = g_xw[base + 2 * HP];
            nx3 = g_xw[base + 3 * HP];
        }

        // ---- layer 1: h1_new = tanh(xw + h1_old @ W1h) ----
        u64t a0 = pack2(xw0, 0.f), a1 = pack2(xw1, 0.f);
        u64t a2 = pack2(xw2, 0.f), a3 = pack2(xw3, 0.f);
        {
            const u64t* wp = (const u64t*)sW1h + u;   // [jp][u] pairs, stride 128
            #pragma unroll
            for (int jp = 0; jp < JP; jp++) {
                ulonglong2 q01 = *(const ulonglong2*)&h1r[jp * 8];      // rows 0,1
                ulonglong2 q23 = *(const ulonglong2*)&h1r[jp * 8 + 4];  // rows 2,3
                u64t w = wp[jp * HP];
                ffma2(a0, q01.x, w);
                ffma2(a1, q01.y, w);
                ffma2(a2, q23.x, w);
                ffma2(a3, q23.y, w);
            }
        }
        float v0 = tanhf(sum2(a0)), v1 = tanhf(sum2(a1));
        float v2 = tanhf(sum2(a2)), v3 = tanhf(sum2(a3));
        if (active) {
            h1w[jpH]     = v0;
            h1w[jpH + 2] = v1;
            h1w[jpH + 4] = v2;
            h1w[jpH + 6] = v3;
        }
        __syncthreads();   // h1_new visible; h1_old reads done

        // ---- layer 2: h2_new = tanh(b2 + h1_new @ W2x + h2_old @ W2h) ----
        float bb = sB2[u];
        u64t c0 = pack2(bb, 0.f), c1 = pack2(bb, 0.f);
        u64t c2 = pack2(bb, 0.f), c3 = pack2(bb, 0.f);
        {
            const u64t* wxp = (const u64t*)sW2x + u;
            const u64t* whp = (const u64t*)sW2h + u;
            #pragma unroll
            for (int jp = 0; jp < JP; jp++) {
                ulonglong2 p01 = *(const ulonglong2*)&h1w[jp * 8];
                ulonglong2 p23 = *(const ulonglong2*)&h1w[jp * 8 + 4];
                ulonglong2 q01 = *(const ulonglong2*)&h2r[jp * 8];
                ulonglong2 q23 = *(const ulonglong2*)&h2r[jp * 8 + 4];
                u64t wa  = wxp[jp * HP];
                u64t wh  = whp[jp * HP];
                ffma2(c0, p01.x, wa); ffma2(c0, q01.x, wh);
                ffma2(c1, p01.y, wa); ffma2(c1, q01.y, wh);
                ffma2(c2, p23.x, wa); ffma2(c2, q23.x, wh);
                ffma2(c3, p23.y, wa); ffma2(c3, q23.y, wh);
            }
        }
        float g0 = tanhf(sum2(c0)), g1 = tanhf(sum2(c1));
        float g2 = tanhf(sum2(c2)), g3 = tanhf(sum2(c3));
        if (active) {
            h2w[jpH]     = g0;
            h2w[jpH + 2] = g1;
            h2w[jpH + 4] = g2;
            h2w[jpH + 6] = g3;
        }
        __syncthreads();   // h2_new visible; h2_old reads done

        xw0 = nx0; xw1 = nx1; xw2 = nx2; xw3 = nx3;
    }

    // ---- epilogue: final state lives in buffer (T&1)==0 (T=512 even) ----
    const float* h1f = sh1;   // buf 0
    const float* h2f = sh2;   // buf 0
    if (active) {
        #pragma unroll
        for (int r = 0; r < 4; r++) {
            float hv1 = h1f[(u >> 1) * 8 + r * 2 + (u & 1)];
            float hv2 = h2f[(u >> 1) * 8 + r * 2 + (u & 1)];
            out[512 + (size_t)(b0 + r) * H + u]         = hv1;
            out[512 + 51200 + (size_t)(b0 + r) * H + u] = hv2;
        }
    }
    if (tid < 4) {
        float s = bo[0];
        for (int j = 0; j < H; j++)
            s += h2f[(j >> 1) * 8 + tid * 2 + (j & 1)] * sWo[j];
        out[b0 + tid] = s;
    }
}

// ---------------------------------------------------------------------------
extern "C" void kernel_launch(void* const* d_in, const int* in_sizes, int n_in,
                              void* d_out, int out_size)
{
    const float* x   = (const float*)d_in[0];
    const float* W1x = (const float*)d_in[1];
    const float* W1h = (const float*)d_in[2];
    const float* b1  = (const float*)d_in[3];
    const float* W2x = (const float*)d_in[4];
    const float* W2h = (const float*)d_in[5];
    const float* b2  = (const float*)d_in[6];
    const float* Wo  = (const float*)d_in[7];
    const float* bo  = (const float*)d_in[8];
    float* out = (float*)d_out;

    cudaFuncSetAttribute(rnn_kernel,
                         cudaFuncAttributeMaxDynamicSharedMemorySize,
                         SMEM_BYTES);

    precompute_xw_kernel<<<dim3(T_STEPS, BATCH / 64), 320>>>(x, W1x, b1);
    rnn_kernel<<<BATCH / 4, 128, SMEM_BYTES>>>(W1h, W2x, W2h, b2, Wo, bo, out);
}

// round 4
// speedup vs baseline: 1.2562x; 1.2562x over previous
#include <cuda_runtime.h>
#include <cuda_bf16.h>
#include <cstddef>

// ---------------------------------------------------------------------------
// DRNN: 2-layer SimpleRNN (tanh), B=512, T=512, D=64, H=100.
//   h1_t = tanh(x_t @ W1x + h1_{t-1} @ W1h + b1)
//   h2_t = tanh(h1_t @ W2x + h2_{t-1} @ W2h + b2)
//   out  = h2_T @ Wo + bo
// d_out: out[512] | h1_T[512*100] | h2_T[512*100]
//
// R3 ncu: rnn kernel was shared-wavefront bound (L1=75%, fma=26%), half the
// wavefronts were loop-invariant weight LDS. This version keeps all three
// recurrent weight matrices in REGISTERS (j split in halves across 2 thread
// groups; 75 packed f32x2 per thread), doubling warps/SMSP and removing
// weight LDS entirely. Cross-half reduction via tiny SMEM scratch.
// ---------------------------------------------------------------------------

#define T_STEPS 512
#define BATCH   512
#define IN_DIM  64
#define H       100
#define HP      128   // padded hidden (u dimension)
#define JPH     25    // j-pairs per half (half covers 50 j values)

typedef unsigned long long u64t;

// scratch: [T][B][HP] floats = 134 MB (zero-initialized at module load; pad
// columns u>=100 are never written and stay 0 -> deterministic)
__device__ float g_xw[(size_t)T_STEPS * BATCH * HP];

__device__ __forceinline__ void ffma2(u64t& d, u64t a, u64t b) {
    asm("fma.rn.f32x2 %0, %1, %2, %0;" : "+l"(d) : "l"(a), "l"(b));
}
__device__ __forceinline__ u64t pack2(float lo, float hi) {
    u64t r;
    asm("mov.b64 %0, {%1, %2};" : "=l"(r) : "f"(lo), "f"(hi));
    return r;
}
__device__ __forceinline__ float sum2(u64t v) {
    float lo, hi;
    asm("mov.b64 {%0, %1}, %2;" : "=f"(lo), "=f"(hi) : "l"(v));
    return lo + hi;
}

// ---------------------------------------------------------------------------
// Kernel 1: precompute xw = b1 + x @ W1x   (grid: 512 t x 8 b-chunks of 64)
// ---------------------------------------------------------------------------
__global__ void __launch_bounds__(320) precompute_xw_kernel(
    const float* __restrict__ x,     // [B][T][D]
    const float* __restrict__ W1x,   // [D][H]
    const float* __restrict__ b1)    // [H]
{
    __shared__ __align__(16) float sW[IN_DIM * H];
    __shared__ float sx[64 * IN_DIM];
    __shared__ float sb1[H];

    const int t   = blockIdx.x;
    const int b0  = blockIdx.y * 64;
    const int tid = threadIdx.x;

    for (int i = tid; i < IN_DIM * H; i += 320) sW[i] = W1x[i];
    for (int i = tid; i < H; i += 320) sb1[i] = b1[i];
    for (int i = tid; i < 64 * IN_DIM; i += 320) {
        int bl = i >> 6, d = i & 63;
        sx[i] = x[(size_t)(b0 + bl) * (T_STEPS * IN_DIM) + (size_t)t * IN_DIM + d];
    }
    __syncthreads();

    #pragma unroll
    for (int k = 0; k < 5; k++) {
        int task = tid + k * 320;
        int bl = task / 25;
        int ug = task % 25;
        int u  = ug * 4;
        float a0 = sb1[u], a1 = sb1[u + 1], a2 = sb1[u + 2], a3 = sb1[u + 3];
        #pragma unroll
        for (int d = 0; d < IN_DIM; d++) {
            float xv = sx[bl * IN_DIM + d];
            float4 w = *(const float4*)&sW[d * H + u];
            a0 += xv * w.x; a1 += xv * w.y; a2 += xv * w.z; a3 += xv * w.w;
        }
        size_t base = (size_t)t * (BATCH * HP) + (size_t)(b0 + bl) * HP + u;
        *(float4*)&g_xw[base] = make_float4(a0, a1, a2, a3);
    }
}

// ---------------------------------------------------------------------------
// Kernel 2: recurrence. 128 blocks x 4 batch rows, 256 threads (8 warps).
//   u    = tid & 127  : hidden unit (100 active, 28 pad)
//   half = tid >> 7   : j-range [half*50, half*50+50)
// Weights live in registers (75 packed f32x2 per thread).
// h state in SMEM [jp][row][2] (j-pair minor), double buffered.
// Per layer: j-loop partials -> STS.64 partner rows -> bar -> reduce+tanh
// (2 rows per thread) -> STS h -> bar.
// ---------------------------------------------------------------------------
#define SM_H1  0      // [2][400]
#define SM_H2  800    // [2][400]
#define SM_SCR 1600   // [2][128][2] = 512
#define SM_WO  2112   // [128]
#define SM_FLOATS 2240

__global__ void __launch_bounds__(256, 1) rnn_kernel(
    const float* __restrict__ W1h,  // [H][H]
    const float* __restrict__ W2x,  // [H][H]
    const float* __restrict__ W2h,  // [H][H]
    const float* __restrict__ b2,   // [H]
    const float* __restrict__ Wo,   // [H][1]
    const float* __restrict__ bo,   // [1]
    float* __restrict__ out)        // [512 + 51200 + 51200]
{
    __shared__ __align__(16) float sm[SM_FLOATS];
    float* sh1 = sm + SM_H1;
    float* sh2 = sm + SM_H2;
    float* scr = sm + SM_SCR;
    float* sWo = sm + SM_WO;

    const int tid  = threadIdx.x;
    const int u    = tid & 127;
    const int hf   = tid >> 7;          // 0 or 1
    const int b0   = blockIdx.x * 4;
    const bool act = (u < H);

    // ---- load weight slices into registers (packed f32x2 over j-pairs) ----
    u64t w1p[JPH], wxp[JPH], whp[JPH];
    #pragma unroll
    for (int jp = 0; jp < JPH; jp++) {
        int j = hf * 50 + 2 * jp;
        float a0 = 0.f, a1 = 0.f, x0 = 0.f, x1 = 0.f, c0 = 0.f, c1 = 0.f;
        if (act) {
            a0 = W1h[j * H + u]; a1 = W1h[(j + 1) * H + u];
            x0 = W2x[j * H + u]; x1 = W2x[(j + 1) * H + u];
            c0 = W2h[j * H + u]; c1 = W2h[(j + 1) * H + u];
        }
        w1p[jp] = pack2(a0, a1);
        wxp[jp] = pack2(x0, x1);
        whp[jp] = pack2(c0, c1);
    }
    const float bb = (act && hf == 0) ? b2[u] : 0.0f;  // bias only in half0
    if (tid < H) sWo[tid] = Wo[tid];
    for (int i = tid; i < 1600; i += 256) sm[i] = 0.0f;  // zero both h bufs
    __syncthreads();

    const int hbase = (u >> 1) * 8 + (u & 1);  // h write base for unit u
    const int hoff  = hf * 200;                // this half's j-offset in h buf

    // prefetch xw for t=0 (half0 only; half0 carries xw into its partials)
    float xw0 = 0.f, xw1 = 0.f, xw2 = 0.f, xw3 = 0.f;
    if (hf == 0) {
        size_t base = (size_t)b0 * HP + u;
        xw0 = g_xw[base];
        xw1 = g_xw[base + HP];
        xw2 = g_xw[base + 2 * HP];
        xw3 = g_xw[base + 3 * HP];
    }

    for (int t = 0; t < T_STEPS; t++) {
        const int rb = (t & 1) * 400;
        const int wb = 400 - rb;
        const float* h1r = sh1 + rb;
        float*       h1w = sh1 + wb;
        const float* h2r = sh2 + rb;
        float*       h2w = sh2 + wb;

        float nx0 = 0.f, nx1 = 0.f, nx2 = 0.f, nx3 = 0.f;
        if (hf == 0 && (t + 1 < T_STEPS)) {
            size_t base = (size_t)(t + 1) * (BATCH * HP) + (size_t)b0 * HP + u;
            nx0 = g_xw[base];
            nx1 = g_xw[base + HP];
            nx2 = g_xw[base + 2 * HP];
            nx3 = g_xw[base + 3 * HP];
        }

        // ---- layer 1 partials: xw(+half0) + sum_{j in my half} h1_old*W1h ----
        u64t a0 = pack2(xw0, 0.f), a1 = pack2(xw1, 0.f);
        u64t a2 = pack2(xw2, 0.f), a3 = pack2(xw3, 0.f);
        #pragma unroll
        for (int jp = 0; jp < JPH; jp++) {
            ulonglong2 q01 = *(const ulonglong2*)&h1r[hoff + jp * 8];      // rows 0,1
            ulonglong2 q23 = *(const ulonglong2*)&h1r[hoff + jp * 8 + 4];  // rows 2,3
            ffma2(a0, q01.x, w1p[jp]);
            ffma2(a1, q01.y, w1p[jp]);
            ffma2(a2, q23.x, w1p[jp]);
            ffma2(a3, q23.y, w1p[jp]);
        }
        {
            float s0 = sum2(a0), s1 = sum2(a1), s2 = sum2(a2), s3 = sum2(a3);
            // hand partner its 2 rows
            float p0 = hf ? s0 : s2;
            float p1 = hf ? s1 : s3;
            *(float2*)&scr[(hf * 128 + u) * 2] = make_float2(p0, p1);
            __syncthreads();
            float2 o = *(const float2*)&scr[((1 - hf) * 128 + u) * 2];
            float m0 = hf ? s2 : s0;
            float m1 = hf ? s3 : s1;
            float v0 = tanhf(m0 + o.x);
            float v1 = tanhf(m1 + o.y);
            if (act) {
                h1w[hbase + (2 * hf) * 2]     = v0;   // row 2*hf
                h1w[hbase + (2 * hf + 1) * 2] = v1;   // row 2*hf+1
            }
        }
        __syncthreads();

        // ---- layer 2 partials: b2(+half0) + h1_new@W2x + h2_old@W2h ----
        u64t c0 = pack2(bb, 0.f), c1 = pack2(bb, 0.f);
        u64t c2 = pack2(bb, 0.f), c3 = pack2(bb, 0.f);
        #pragma unroll
        for (int jp = 0; jp < JPH; jp++) {
            ulonglong2 p01 = *(const ulonglong2*)&h1w[hoff + jp * 8];
            ulonglong2 p23 = *(const ulonglong2*)&h1w[hoff + jp * 8 + 4];
            ulonglong2 q01 = *(const ulonglong2*)&h2r[hoff + jp * 8];
            ulonglong2 q23 = *(const ulonglong2*)&h2r[hoff + jp * 8 + 4];
            ffma2(c0, p01.x, wxp[jp]); ffma2(c0, q01.x, whp[jp]);
            ffma2(c1, p01.y, wxp[jp]); ffma2(c1, q01.y, whp[jp]);
            ffma2(c2, p23.x, wxp[jp]); ffma2(c2, q23.x, whp[jp]);
            ffma2(c3, p23.y, wxp[jp]); ffma2(c3, q23.y, whp[jp]);
        }
        {
            float s0 = sum2(c0), s1 = sum2(c1), s2 = sum2(c2), s3 = sum2(c3);
            float p0 = hf ? s0 : s2;
            float p1 = hf ? s1 : s3;
            *(float2*)&scr[(hf * 128 + u) * 2] = make_float2(p0, p1);
            __syncthreads();
            float2 o = *(const float2*)&scr[((1 - hf) * 128 + u) * 2];
            float m0 = hf ? s2 : s0;
            float m1 = hf ? s3 : s1;
            float g0 = tanhf(m0 + o.x);
            float g1 = tanhf(m1 + o.y);
            if (act) {
                h2w[hbase + (2 * hf) * 2]     = g0;
                h2w[hbase + (2 * hf + 1) * 2] = g1;
            }
        }
        __syncthreads();

        xw0 = nx0; xw1 = nx1; xw2 = nx2; xw3 = nx3;
    }

    // ---- epilogue: final state is in buffer 0 (T even) ----
    const float* h1f = sh1;
    const float* h2f = sh2;
    if (act && hf == 0) {
        #pragma unroll
        for (int r = 0; r < 4; r++) {
            float hv1 = h1f[(u >> 1) * 8 + r * 2 + (u & 1)];
            float hv2 = h2f[(u >> 1) * 8 + r * 2 + (u & 1)];
            out[512 + (size_t)(b0 + r) * H + u]         = hv1;
            out[512 + 51200 + (size_t)(b0 + r) * H + u] = hv2;
        }
    }
    if (tid < 4) {
        float s = bo[0];
        for (int j = 0; j < H; j++)
            s += h2f[(j >> 1) * 8 + tid * 2 + (j & 1)] * sWo[j];
        out[b0 + tid] = s;
    }
}

// ---------------------------------------------------------------------------
extern "C" void kernel_launch(void* const* d_in, const int* in_sizes, int n_in,
                              void* d_out, int out_size)
{
    const float* x   = (const float*)d_in[0];
    const float* W1x = (const float*)d_in[1];
    const float* W1h = (const float*)d_in[2];
    const float* b1  = (const float*)d_in[3];
    const float* W2x = (const float*)d_in[4];
    const float* W2h = (const float*)d_in[5];
    const float* b2  = (const float*)d_in[6];
    const float* Wo  = (const float*)d_in[7];
    const float* bo  = (const float*)d_in[8];
    float* out = (float*)d_out;

    precompute_xw_kernel<<<dim3(T_STEPS, BATCH / 64), 320>>>(x, W1x, b1);
    rnn_kernel<<<BATCH / 4, 256>>>(W1h, W2x, W2h, b2, Wo, bo, out);
}

// round 5
// speedup vs baseline: 1.3092x; 1.0422x over previous
#include <cuda_runtime.h>
#include <cuda_bf16.h>
#include <cstddef>

// ---------------------------------------------------------------------------
// DRNN: 2-layer SimpleRNN (tanh), B=512, T=512, D=64, H=100.
//   h1_t = tanh(x_t @ W1x + h1_{t-1} @ W1h + b1)
//   h2_t = tanh(h1_t @ W2x + h2_{t-1} @ W2h + b2)
//   out  = h2_T @ Wo + bo
// d_out: out[512] | h1_T[512*100] | h2_T[512*100]
//
// R4 ncu: still L1-bound (70.9%) — h-state reuse per LDS was 1. This version:
// each thread owns U=2 hidden units (halving h loads), j split in S=4 slices
// mapped to lane bits so a 6-shfl butterfly reduce-scatters rows to slices
// (lane slice s finishes holding row s). Weights in registers. Custom
// ex2/rcp tanh. Precompute kernel: 8 rows/thread f32x2 + replicated weights.
// ---------------------------------------------------------------------------

#define T_STEPS 512
#define BATCH   512
#define IN_DIM  64
#define H       100
#define HP      128        // padded u (xw scratch stride)
#define JPS     13         // j-pairs per slice (4 slices * 13 = 52 pairs = 104 j)

typedef unsigned long long u64t;

// scratch: [T][B][HP] floats = 134 MB
__device__ float g_xw[(size_t)T_STEPS * BATCH * HP];

__device__ __forceinline__ void ffma2(u64t& d, u64t a, u64t b) {
    asm("fma.rn.f32x2 %0, %1, %2, %0;" : "+l"(d) : "l"(a), "l"(b));
}
__device__ __forceinline__ u64t pack2(float lo, float hi) {
    u64t r;
    asm("mov.b64 %0, {%1, %2};" : "=l"(r) : "f"(lo), "f"(hi));
    return r;
}
__device__ __forceinline__ void unpack2(float& lo, float& hi, u64t v) {
    asm("mov.b64 {%0, %1}, %2;" : "=f"(lo), "=f"(hi) : "l"(v));
}
__device__ __forceinline__ float sum2(u64t v) {
    float lo, hi;
    unpack2(lo, hi, v);
    return lo + hi;
}
// tanh via exp(2x): ~8 instrs, 2 MUFU, abs err ~1e-7. Clamp avoids inf/inf.
__device__ __forceinline__ float fast_tanh(float x) {
    x = fminf(fmaxf(x, -15.0f), 15.0f);
    float e;
    asm("ex2.approx.f32 %0, %1;" : "=f"(e) : "f"(x * 2.885390081777927f)); // 2*log2(e)
    float r;
    asm("rcp.approx.f32 %0, %1;" : "=f"(r) : "f"(e + 1.0f));
    return (e - 1.0f) * r;
}

// ---------------------------------------------------------------------------
// Kernel 1: xw[t][b][u] = b1[u] + x[b][t][:] @ W1x[:][u]
// grid (512 t, 8 chunks of 64 rows), 200 threads: thread = (ug 0..24)x(ro 0..7)
// 8 rows packed as 4 f32x2 row-pairs; weights SMEM-replicated [d][u][2] so
// FFMA2 needs no pack instructions.
// ---------------------------------------------------------------------------
#define PC_THREADS 200

__global__ void __launch_bounds__(PC_THREADS) precompute_xw_kernel(
    const float* __restrict__ x,     // [B][T][D]
    const float* __restrict__ W1x,   // [D][H]
    const float* __restrict__ b1)    // [H]
{
    __shared__ __align__(16) float sWr[IN_DIM * H * 2];  // [d][u][2] replicated
    __shared__ __align__(16) float sxT[IN_DIM * 64];     // [d][row]

    const int t   = blockIdx.x;
    const int b0  = blockIdx.y * 64;
    const int tid = threadIdx.x;

    for (int i = tid; i < IN_DIM * H; i += PC_THREADS) {
        float w = W1x[i];
        sWr[2 * i] = w; sWr[2 * i + 1] = w;
    }
    for (int i = tid; i < 64 * IN_DIM; i += PC_THREADS) {
        int bl = i >> 6, d = i & 63;
        sxT[d * 64 + bl] =
            x[(size_t)(b0 + bl) * (T_STEPS * IN_DIM) + (size_t)t * IN_DIM + d];
    }
    __syncthreads();

    const int ug = tid >> 3;     // 0..24 -> u = 4*ug
    const int ro = tid & 7;      // row-oct: rows ro*8 .. ro*8+7
    const int u  = ug * 4;

    u64t acc[4][4];              // [u-local][row-pair]
    #pragma unroll
    for (int ul = 0; ul < 4; ul++) {
        float b = b1[u + ul];
        #pragma unroll
        for (int rp = 0; rp < 4; rp++) acc[ul][rp] = pack2(b, b);
    }

    #pragma unroll 8
    for (int d = 0; d < IN_DIM; d++) {
        ulonglong2 x01 = *(const ulonglong2*)&sxT[d * 64 + ro * 8];      // rows +0..3
        ulonglong2 x23 = *(const ulonglong2*)&sxT[d * 64 + ro * 8 + 4];  // rows +4..7
        ulonglong2 wq0 = *(const ulonglong2*)&sWr[(d * H + u) * 2];      // (w0,w0),(w1,w1)
        ulonglong2 wq1 = *(const ulonglong2*)&sWr[(d * H + u) * 2 + 4];  // (w2,w2),(w3,w3)
        ffma2(acc[0][0], x01.x, wq0.x); ffma2(acc[0][1], x01.y, wq0.x);
        ffma2(acc[0][2], x23.x, wq0.x); ffma2(acc[0][3], x23.y, wq0.x);
        ffma2(acc[1][0], x01.x, wq0.y); ffma2(acc[1][1], x01.y, wq0.y);
        ffma2(acc[1][2], x23.x, wq0.y); ffma2(acc[1][3], x23.y, wq0.y);
        ffma2(acc[2][0], x01.x, wq1.x); ffma2(acc[2][1], x01.y, wq1.x);
        ffma2(acc[2][2], x23.x, wq1.x); ffma2(acc[2][3], x23.y, wq1.x);
        ffma2(acc[3][0], x01.x, wq1.y); ffma2(acc[3][1], x01.y, wq1.y);
        ffma2(acc[3][2], x23.x, wq1.y); ffma2(acc[3][3], x23.y, wq1.y);
    }

    #pragma unroll
    for (int rp = 0; rp < 4; rp++) {
        float l0, h0, l1, h1, l2, h2, l3, h3;
        unpack2(l0, h0, acc[0][rp]);
        unpack2(l1, h1, acc[1][rp]);
        unpack2(l2, h2, acc[2][rp]);
        unpack2(l3, h3, acc[3][rp]);
        int r0 = ro * 8 + rp * 2;
        size_t base = (size_t)t * (BATCH * HP) + (size_t)(b0 + r0) * HP + u;
        *(float4*)&g_xw[base]      = make_float4(l0, l1, l2, l3);
        *(float4*)&g_xw[base + HP] = make_float4(h0, h1, h2, h3);
    }
}

// ---------------------------------------------------------------------------
// Kernel 2: recurrence. 128 blocks x 4 batch rows, 256 threads (8 warps).
//   lane = s (slice, bits 0-1) | g (u-group-in-warp, bits 2-4)
//   thread owns u-pair u0=2*(warp*8+g) and j-slice s (13 j-pairs).
// h state SMEM [jp][row][2], double buffered. Per layer: register-weight
// FFMA2 partials -> 6-shfl butterfly (lane slice s ends with row s fully
// reduced) -> +xw/bias -> tanh -> STS.64 -> __syncthreads.
// ---------------------------------------------------------------------------
__global__ void __launch_bounds__(256, 1) rnn_kernel(
    const float* __restrict__ W1h,  // [H][H]
    const float* __restrict__ W2x,  // [H][H]
    const float* __restrict__ W2h,  // [H][H]
    const float* __restrict__ b2,   // [H]
    const float* __restrict__ Wo,   // [H][1]
    const float* __restrict__ bo,   // [1]
    float* __restrict__ out)        // [512 + 51200 + 51200]
{
    __shared__ __align__(16) float sh1[832];   // [2][52][4][2]
    __shared__ __align__(16) float sh2[832];
    __shared__ float sWo[HP];

    const int tid  = threadIdx.x;
    const int lane = tid & 31;
    const int wrp  = tid >> 5;
    const int s    = lane & 3;           // slice / output row
    const int g    = lane >> 2;          // 0..7
    const int up   = wrp * 8 + g;        // u-pair 0..63
    const int u0   = up * 2;             // 0..126 (active: <100)
    const int b0   = blockIdx.x * 4;
    const int s0   = s & 1;
    const int s1   = s >> 1;
    const bool wr  = (u0 < H);           // this thread writes h

    // ---- weights into registers: [ul][jp] packed f32x2 over j-pair ----
    u64t w1p[2][JPS], wxp[2][JPS], whp[2][JPS];
    #pragma unroll
    for (int jp = 0; jp < JPS; jp++) {
        const int j = s * (2 * JPS) + 2 * jp;   // global j (0..102)
        #pragma unroll
        for (int ul = 0; ul < 2; ul++) {
            const int u = u0 + ul;
            float a0 = 0.f, a1 = 0.f, x0 = 0.f, x1 = 0.f, c0 = 0.f, c1 = 0.f;
            if (u < H) {
                if (j < H)     { a0 = W1h[j * H + u];       x0 = W2x[j * H + u];       c0 = W2h[j * H + u]; }
                if (j + 1 < H) { a1 = W1h[(j + 1) * H + u]; x1 = W2x[(j + 1) * H + u]; c1 = W2h[(j + 1) * H + u]; }
            }
            w1p[ul][jp] = pack2(a0, a1);
            wxp[ul][jp] = pack2(x0, x1);
            whp[ul][jp] = pack2(c0, c1);
        }
    }
    const float bias0 = (u0 < H)     ? b2[u0]     : 0.f;
    const float bias1 = (u0 + 1 < H) ? b2[u0 + 1] : 0.f;
    if (tid < H) sWo[tid] = Wo[tid];
    for (int i = tid; i < 832; i += 256) { sh1[i] = 0.f; sh2[i] = 0.f; }
    __syncthreads();

    // xw for this thread's (u0,u1) at its output row s
    const float* xwptr = g_xw + (size_t)(b0 + s) * HP + u0;
    float2 xwc = *(const float2*)xwptr;

    const int sbase = s * (JPS * 8);     // slice offset in h buffer
    const int wpos  = up * 8 + s * 2;    // h write position [jp=up][row=s][0..1]

    for (int t = 0; t < T_STEPS; t++) {
        const int rb = (t & 1) * 416;
        const int wb = 416 - rb;
        const float* h1r = sh1 + rb + sbase;
        const float* h1n = sh1 + wb + sbase;   // read in layer2 after bar
        const float* h2r = sh2 + rb + sbase;

        float2 xwn = make_float2(0.f, 0.f);
        if (t + 1 < T_STEPS)
            xwn = *(const float2*)(xwptr + (size_t)(t + 1) * (BATCH * HP));

        // ================= layer 1 =================
        u64t a00 = 0, a01 = 0, a02 = 0, a03 = 0;   // ul=0, rows 0..3 (j-pair partials)
        u64t a10 = 0, a11 = 0, a12 = 0, a13 = 0;   // ul=1
        #pragma unroll
        for (int jp = 0; jp < JPS; jp++) {
            ulonglong2 q01 = *(const ulonglong2*)&h1r[jp * 8];
            ulonglong2 q23 = *(const ulonglong2*)&h1r[jp * 8 + 4];
            ffma2(a00, q01.x, w1p[0][jp]); ffma2(a01, q01.y, w1p[0][jp]);
            ffma2(a02, q23.x, w1p[0][jp]); ffma2(a03, q23.y, w1p[0][jp]);
            ffma2(a10, q01.x, w1p[1][jp]); ffma2(a11, q01.y, w1p[1][jp]);
            ffma2(a12, q23.x, w1p[1][jp]); ffma2(a13, q23.y, w1p[1][jp]);
        }
        {
            float v00 = sum2(a00), v01 = sum2(a01), v02 = sum2(a02), v03 = sum2(a03);
            float v10 = sum2(a10), v11 = sum2(a11), v12 = sum2(a12), v13 = sum2(a13);
            // butterfly reduce-scatter: slice s keeps row s
            float sA0 = s0 ? v00 : v01, sB0 = s0 ? v02 : v03;
            float sA1 = s0 ? v10 : v11, sB1 = s0 ? v12 : v13;
            sA0 = __shfl_xor_sync(0xffffffffu, sA0, 1);
            sB0 = __shfl_xor_sync(0xffffffffu, sB0, 1);
            sA1 = __shfl_xor_sync(0xffffffffu, sA1, 1);
            sB1 = __shfl_xor_sync(0xffffffffu, sB1, 1);
            float kA0 = (s0 ? v01 : v00) + sA0;   // row s0
            float kB0 = (s0 ? v03 : v02) + sB0;   // row s0+2
            float kA1 = (s0 ? v11 : v10) + sA1;
            float kB1 = (s0 ? v13 : v12) + sB1;
            float t0 = s1 ? kA0 : kB0;
            float t1 = s1 ? kA1 : kB1;
            t0 = __shfl_xor_sync(0xffffffffu, t0, 2);
            t1 = __shfl_xor_sync(0xffffffffu, t1, 2);
            float fin0 = (s1 ? kB0 : kA0) + t0 + xwc.x;
            float fin1 = (s1 ? kB1 : kA1) + t1 + xwc.y;
            fin0 = fast_tanh(fin0);
            fin1 = fast_tanh(fin1);
            if (wr) *(float2*)&sh1[wb + wpos] = make_float2(fin0, fin1);
        }
        __syncthreads();   // h1_new visible everywhere

        // ================= layer 2 =================
        u64t c00 = 0, c01 = 0, c02 = 0, c03 = 0;
        u64t c10 = 0, c11 = 0, c12 = 0, c13 = 0;
        #pragma unroll
        for (int jp = 0; jp < JPS; jp++) {
            ulonglong2 p01 = *(const ulonglong2*)&h1n[jp * 8];
            ulonglong2 p23 = *(const ulonglong2*)&h1n[jp * 8 + 4];
            ulonglong2 q01 = *(const ulonglong2*)&h2r[jp * 8];
            ulonglong2 q23 = *(const ulonglong2*)&h2r[jp * 8 + 4];
            ffma2(c00, p01.x, wxp[0][jp]); ffma2(c00, q01.x, whp[0][jp]);
            ffma2(c01, p01.y, wxp[0][jp]); ffma2(c01, q01.y, whp[0][jp]);
            ffma2(c02, p23.x, wxp[0][jp]); ffma2(c02, q23.x, whp[0][jp]);
            ffma2(c03, p23.y, wxp[0][jp]); ffma2(c03, q23.y, whp[0][jp]);
            ffma2(c10, p01.x, wxp[1][jp]); ffma2(c10, q01.x, whp[1][jp]);
            ffma2(c11, p01.y, wxp[1][jp]); ffma2(c11, q01.y, whp[1][jp]);
            ffma2(c12, p23.x, wxp[1][jp]); ffma2(c12, q23.x, whp[1][jp]);
            ffma2(c13, p23.y, wxp[1][jp]); ffma2(c13, q23.y, whp[1][jp]);
        }
        {
            float v00 = sum2(c00), v01 = sum2(c01), v02 = sum2(c02), v03 = sum2(c03);
            float v10 = sum2(c10), v11 = sum2(c11), v12 = sum2(c12), v13 = sum2(c13);
            float sA0 = s0 ? v00 : v01, sB0 = s0 ? v02 : v03;
            float sA1 = s0 ? v10 : v11, sB1 = s0 ? v12 : v13;
            sA0 = __shfl_xor_sync(0xffffffffu, sA0, 1);
            sB0 = __shfl_xor_sync(0xffffffffu, sB0, 1);
            sA1 = __shfl_xor_sync(0xffffffffu, sA1, 1);
            sB1 = __shfl_xor_sync(0xffffffffu, sB1, 1);
            float kA0 = (s0 ? v01 : v00) + sA0;
            float kB0 = (s0 ? v03 : v02) + sB0;
            float kA1 = (s0 ? v11 : v10) + sA1;
            float kB1 = (s0 ? v13 : v12) + sB1;
            float t0 = s1 ? kA0 : kB0;
            float t1 = s1 ? kA1 : kB1;
            t0 = __shfl_xor_sync(0xffffffffu, t0, 2);
            t1 = __shfl_xor_sync(0xffffffffu, t1, 2);
            float fin0 = (s1 ? kB0 : kA0) + t0 + bias0;
            float fin1 = (s1 ? kB1 : kA1) + t1 + bias1;
            fin0 = fast_tanh(fin0);
            fin1 = fast_tanh(fin1);
            if (wr) *(float2*)&sh2[wb + wpos] = make_float2(fin0, fin1);
        }
        __syncthreads();   // h2_new visible; old buffers free for next step

        xwc = xwn;
    }

    // ---- epilogue: final state in buffer 0 (T even) ----
    for (int i = tid; i < 4 * H; i += 256) {
        int r = i / H;
        int u = i - r * H;
        int pos = (u >> 1) * 8 + r * 2 + (u & 1);
        out[512 + (size_t)(b0 + r) * H + u]         = sh1[pos];
        out[512 + 51200 + (size_t)(b0 + r) * H + u] = sh2[pos];
    }
    if (tid < 4) {
        float sacc = bo[0];
        for (int j = 0; j < H; j++)
            sacc += sh2[(j >> 1) * 8 + tid * 2 + (j & 1)] * sWo[j];
        out[b0 + tid] = sacc;
    }
}

// ---------------------------------------------------------------------------
extern "C" void kernel_launch(void* const* d_in, const int* in_sizes, int n_in,
                              void* d_out, int out_size)
{
    const float* x   = (const float*)d_in[0];
    const float* W1x = (const float*)d_in[1];
    const float* W1h = (const float*)d_in[2];
    const float* b1  = (const float*)d_in[3];
    const float* W2x = (const float*)d_in[4];
    const float* W2h = (const float*)d_in[5];
    const float* b2  = (const float*)d_in[6];
    const float* Wo  = (const float*)d_in[7];
    const float* bo  = (const float*)d_in[8];
    float* out = (float*)d_out;

    precompute_xw_kernel<<<dim3(T_STEPS, BATCH / 64), PC_THREADS>>>(x, W1x, b1);
    rnn_kernel<<<BATCH / 4, 256>>>(W1h, W2x, W2h, b2, Wo, bo, out);
}